// round 1
// baseline (speedup 1.0000x reference)
#include <cuda_runtime.h>
#include <math.h>

// Problem constants (fixed by the reference)
constexpr int Bsz = 2;
constexpr int Hn  = 16;
constexpr int Sn  = 2048;
constexpr int Dn  = 128;

constexpr int BQ = 64;    // q-tile rows per CTA
constexpr int BK = 64;    // k-tile cols per iteration
constexpr int NT = 256;   // threads per CTA

// Shared memory layout (floats):
//   qT : [Dn][BQ]  (Q transposed -> broadcast-friendly reads)
//   kT : [Dn][BK]  (K transposed -> conflict-free float4 reads)
//   vs : [BK][Dn]  (V row-major  -> conflict-free float4 reads)
//   ps : [BQ][BK]  (softmax probabilities)
constexpr int SMEM_FLOATS = Dn*BQ + Dn*BK + BK*Dn + BQ*BK;
constexpr int SMEM_BYTES  = SMEM_FLOATS * 4;   // 114688 B

__global__ __launch_bounds__(NT)
void fa_causal_fp32_kernel(const float* __restrict__ q,
                           const float* __restrict__ k,
                           const float* __restrict__ v,
                           const float* __restrict__ attn_mask,   // [B, S]
                           const float* __restrict__ head_mask,   // [H]
                           float* __restrict__ out)
{
    extern __shared__ float sm[];
    float* qT = sm;                    // Dn*BQ
    float* kT = qT + Dn*BQ;            // Dn*BK
    float* vs = kT + Dn*BK;            // BK*Dn
    float* ps = vs + BK*Dn;            // BQ*BK

    const int bh = blockIdx.y;                 // 0..B*H-1
    const int b  = bh >> 4;                    // H == 16
    const int h  = bh & 15;
    // Reverse q-tile order so heavy (long-causal) tiles launch first.
    const int qt = (int)gridDim.x - 1 - (int)blockIdx.x;
    const int q0 = qt * BQ;

    const float* qg  = q + ((size_t)bh * Sn + q0) * Dn;
    const float* kg  = k + (size_t)bh * Sn * Dn;
    const float* vg  = v + (size_t)bh * Sn * Dn;
    const float* amg = attn_mask + (size_t)b * Sn;
    const float  hmask = head_mask[h];

    const int tid = threadIdx.x;
    const int tr  = tid >> 4;   // 0..15 : owns q rows tr*4 .. tr*4+3
    const int tc  = tid & 15;   // 0..15 : owns k cols tc*4 .. tc*4+3 (and out cols tc*8..tc*8+7)

    // ---- load Q tile transposed into smem ----
    #pragma unroll
    for (int it = 0; it < (BQ * Dn / 4) / NT; ++it) {
        int e   = it * NT + tid;          // float4 index; Dn/4 == 32
        int row = e >> 5;
        int d4  = e & 31;
        float4 val = reinterpret_cast<const float4*>(qg)[e];
        qT[(d4 * 4 + 0) * BQ + row] = val.x;
        qT[(d4 * 4 + 1) * BQ + row] = val.y;
        qT[(d4 * 4 + 2) * BQ + row] = val.z;
        qT[(d4 * 4 + 3) * BQ + row] = val.w;
    }

    float o[4][8];
    #pragma unroll
    for (int i = 0; i < 4; ++i)
        #pragma unroll
        for (int c = 0; c < 8; ++c) o[i][c] = 0.0f;

    float Mrow[4], Lrow[4];
    #pragma unroll
    for (int i = 0; i < 4; ++i) { Mrow[i] = -INFINITY; Lrow[i] = 0.0f; }

    for (int kt = 0; kt <= qt; ++kt) {
        const float* kgt = kg + (size_t)kt * BK * Dn;
        const float* vgt = vg + (size_t)kt * BK * Dn;

        __syncthreads();   // previous iteration's consumers done (also covers Q load on iter 0)

        // ---- load K tile (transposed) and V tile ----
        #pragma unroll
        for (int it = 0; it < (BK * Dn / 4) / NT; ++it) {
            int e   = it * NT + tid;
            int row = e >> 5;
            int d4  = e & 31;
            float4 val = reinterpret_cast<const float4*>(kgt)[e];
            kT[(d4 * 4 + 0) * BK + row] = val.x;
            kT[(d4 * 4 + 1) * BK + row] = val.y;
            kT[(d4 * 4 + 2) * BK + row] = val.z;
            kT[(d4 * 4 + 3) * BK + row] = val.w;
            reinterpret_cast<float4*>(vs)[e] =
                reinterpret_cast<const float4*>(vgt)[e];
        }
        __syncthreads();

        // ---- S = Q K^T  (4x4 micro-tile per thread) ----
        float sacc[4][4];
        #pragma unroll
        for (int i = 0; i < 4; ++i)
            #pragma unroll
            for (int j = 0; j < 4; ++j) sacc[i][j] = 0.0f;

        #pragma unroll 4
        for (int d = 0; d < Dn; ++d) {
            float4 qv = *reinterpret_cast<const float4*>(&qT[d * BQ + tr * 4]); // broadcast in half-warp
            float4 kv = *reinterpret_cast<const float4*>(&kT[d * BK + tc * 4]); // conflict-free
            float qa[4] = {qv.x, qv.y, qv.z, qv.w};
            float ka[4] = {kv.x, kv.y, kv.z, kv.w};
            #pragma unroll
            for (int i = 0; i < 4; ++i)
                #pragma unroll
                for (int j = 0; j < 4; ++j)
                    sacc[i][j] += qa[i] * ka[j];
        }

        // ---- causal mask (before additive mask, matching reference) + attn_mask ----
        const bool diag = (kt == qt);
        #pragma unroll
        for (int j = 0; j < 4; ++j) {
            int colg = kt * BK + tc * 4 + j;
            float amv = amg[colg];
            #pragma unroll
            for (int i = 0; i < 4; ++i) {
                if (diag && (tc * 4 + j) > (tr * 4 + i))
                    sacc[i][j] = -INFINITY;
                else
                    sacc[i][j] += amv;
            }
        }

        // ---- online softmax (per-row reduce over the 16-lane tc group) ----
        #pragma unroll
        for (int i = 0; i < 4; ++i) {
            float rm = fmaxf(fmaxf(sacc[i][0], sacc[i][1]),
                             fmaxf(sacc[i][2], sacc[i][3]));
            #pragma unroll
            for (int off = 8; off >= 1; off >>= 1)
                rm = fmaxf(rm, __shfl_xor_sync(0xffffffffu, rm, off));

            float Mn = fmaxf(Mrow[i], rm);
            float sc = __expf(Mrow[i] - Mn);   // 0 on first valid tile (exp(-inf))

            float p0 = __expf(sacc[i][0] - Mn);
            float p1 = __expf(sacc[i][1] - Mn);
            float p2 = __expf(sacc[i][2] - Mn);
            float p3 = __expf(sacc[i][3] - Mn);

            float rs = (p0 + p1) + (p2 + p3);
            #pragma unroll
            for (int off = 8; off >= 1; off >>= 1)
                rs += __shfl_xor_sync(0xffffffffu, rs, off);

            Lrow[i] = Lrow[i] * sc + rs;
            Mrow[i] = Mn;
            #pragma unroll
            for (int c = 0; c < 8; ++c) o[i][c] *= sc;

            float4 pv4 = make_float4(p0, p1, p2, p3);
            *reinterpret_cast<float4*>(&ps[(tr * 4 + i) * BK + tc * 4]) = pv4;
        }
        __syncthreads();

        // ---- O += P V ----
        #pragma unroll 2
        for (int kk = 0; kk < BK; ++kk) {
            float4 v0 = *reinterpret_cast<const float4*>(&vs[kk * Dn + tc * 8]);
            float4 v1 = *reinterpret_cast<const float4*>(&vs[kk * Dn + tc * 8 + 4]);
            #pragma unroll
            for (int i = 0; i < 4; ++i) {
                float pvv = ps[(tr * 4 + i) * BK + kk];  // broadcast in half-warp
                o[i][0] += pvv * v0.x;
                o[i][1] += pvv * v0.y;
                o[i][2] += pvv * v0.z;
                o[i][3] += pvv * v0.w;
                o[i][4] += pvv * v1.x;
                o[i][5] += pvv * v1.y;
                o[i][6] += pvv * v1.z;
                o[i][7] += pvv * v1.w;
            }
        }
    }

    // ---- epilogue: normalize, apply head_mask, store ----
    #pragma unroll
    for (int i = 0; i < 4; ++i) {
        float inv = hmask / Lrow[i];
        int row = q0 + tr * 4 + i;
        float* og = out + ((size_t)bh * Sn + row) * Dn + tc * 8;
        float4 r0 = make_float4(o[i][0]*inv, o[i][1]*inv, o[i][2]*inv, o[i][3]*inv);
        float4 r1 = make_float4(o[i][4]*inv, o[i][5]*inv, o[i][6]*inv, o[i][7]*inv);
        reinterpret_cast<float4*>(og)[0] = r0;
        reinterpret_cast<float4*>(og)[1] = r1;
    }
}

extern "C" void kernel_launch(void* const* d_in, const int* in_sizes, int n_in,
                              void* d_out, int out_size)
{
    const float* q  = (const float*)d_in[0];
    const float* k  = (const float*)d_in[1];
    const float* v  = (const float*)d_in[2];
    const float* am = (const float*)d_in[3];
    const float* hm = (const float*)d_in[4];
    float* out = (float*)d_out;

    cudaFuncSetAttribute(fa_causal_fp32_kernel,
                         cudaFuncAttributeMaxDynamicSharedMemorySize, SMEM_BYTES);

    dim3 grid(Sn / BQ, Bsz * Hn);   // (32 q-tiles, 32 batch*head)
    fa_causal_fp32_kernel<<<grid, NT, SMEM_BYTES>>>(q, k, v, am, hm, out);
}

// round 3
// speedup vs baseline: 4.5824x; 4.5824x over previous
#include <cuda_runtime.h>
#include <cuda_bf16.h>
#include <cstdint>
#include <math.h>

// ===================== problem constants =====================
constexpr int Bsz = 2;
constexpr int Hn  = 16;
constexpr int Sn  = 2048;
constexpr int Dh  = 128;

constexpr int BQ = 128;   // q rows per CTA (8 warps x 16 rows)
constexpr int BK = 64;    // k cols per iteration
constexpr int NT = 256;   // 8 warps

constexpr int RSB = 272;  // smem row stride in bytes (136 bf16) -> conflict-free ldmatrix

// smem byte offsets
constexpr int SM_QHI = 0;
constexpr int SM_QLO = SM_QHI + BQ * RSB;
constexpr int SM_KHI = SM_QLO + BQ * RSB;
constexpr int SM_KLO = SM_KHI + BK * RSB;
constexpr int SM_VHI = SM_KLO + BK * RSB;
constexpr int SM_VLO = SM_VHI + BK * RSB;
constexpr int SM_AM  = SM_VLO + BK * RSB;
constexpr int SM_TOTAL = SM_AM + BK * 4;       // ~139.8 KB

// ===================== helpers =====================
static __device__ __forceinline__ uint32_t smem_u32(const void* p) {
    uint32_t a;
    asm("{ .reg .u64 t; cvta.to.shared.u64 t, %1; cvt.u32.u64 %0, t; }" : "=r"(a) : "l"(p));
    return a;
}
static __device__ __forceinline__ void ldsm4(uint32_t* r, uint32_t a) {
    asm volatile("ldmatrix.sync.aligned.m8n8.x4.shared.b16 {%0,%1,%2,%3}, [%4];"
                 : "=r"(r[0]), "=r"(r[1]), "=r"(r[2]), "=r"(r[3]) : "r"(a));
}
static __device__ __forceinline__ void ldsm4t(uint32_t* r, uint32_t a) {
    asm volatile("ldmatrix.sync.aligned.m8n8.x4.trans.shared.b16 {%0,%1,%2,%3}, [%4];"
                 : "=r"(r[0]), "=r"(r[1]), "=r"(r[2]), "=r"(r[3]) : "r"(a));
}
static __device__ __forceinline__ void mma_bf16(float* c, const uint32_t* a, const uint32_t* b) {
    asm volatile("mma.sync.aligned.m16n8k16.row.col.f32.bf16.bf16.f32 "
                 "{%0,%1,%2,%3},{%4,%5,%6,%7},{%8,%9},{%0,%1,%2,%3};"
                 : "+f"(c[0]), "+f"(c[1]), "+f"(c[2]), "+f"(c[3])
                 : "r"(a[0]), "r"(a[1]), "r"(a[2]), "r"(a[3]), "r"(b[0]), "r"(b[1]));
}
// pack two f32 -> bf16x2 (lo in low half)
static __device__ __forceinline__ uint32_t cvt2(float lo, float hi) {
    uint32_t r;
    asm("cvt.rn.bf16x2.f32 %0, %1, %2;" : "=r"(r) : "f"(hi), "f"(lo));
    return r;
}
static __device__ __forceinline__ float bflo(uint32_t u) { return __uint_as_float(u << 16); }
static __device__ __forceinline__ float bfhi(uint32_t u) { return __uint_as_float(u & 0xffff0000u); }

// software exp on FMA pipe (x <= 0 expected; handles -inf / -1e30 -> ~0)
static __device__ __forceinline__ float fexp(float x) {
    x = fmaxf(x, -87.3f);
    const float L2E = 1.4426950408889634f;
    float r = fmaf(x, L2E, 12582912.0f);          // round(y) via magic
    float n = r - 12582912.0f;
    float t = fmaf(x, L2E, -n);                   // frac in [-0.5, 0.5]
    float p =              1.5403530393e-4f;
    p = fmaf(p, t, 1.3333558146e-3f);
    p = fmaf(p, t, 9.6181291076e-3f);
    p = fmaf(p, t, 5.5504108665e-2f);
    p = fmaf(p, t, 2.4022650696e-1f);
    p = fmaf(p, t, 6.9314718056e-1f);
    p = fmaf(p, t, 1.0f);
    int sc = (__float_as_int(r) - 0x4B400000) << 23;   // n << 23
    return __uint_as_float(__float_as_int(p) + sc);
}

// ===================== kernel =====================
__global__ __launch_bounds__(NT, 1)
void fa_mma_kernel(const float* __restrict__ q, const float* __restrict__ k,
                   const float* __restrict__ v, const float* __restrict__ am,
                   const float* __restrict__ hm, float* __restrict__ out)
{
    extern __shared__ char smem[];
    const uint32_t sbase = smem_u32(smem);
    float* am_s = reinterpret_cast<float*>(smem + SM_AM);

    const int tid = threadIdx.x, wid = tid >> 5, lane = tid & 31;
    const int bh = blockIdx.y, b = bh >> 4, h = bh & 15;
    const int qt = (int)gridDim.x - 1 - (int)blockIdx.x;   // heavy tiles first
    const int q0 = qt * BQ;
    const int nkt = 2 * (qt + 1);

    const float* qg  = q + ((size_t)bh * Sn + q0) * Dh;
    const float* kg  = k + (size_t)bh * Sn * Dh;
    const float* vg  = v + (size_t)bh * Sn * Dh;
    const float* amg = am + (size_t)b * Sn;
    const float  hmv = hm[h];

    // ---- load Q tile, split fp32 -> bf16 hi/lo ----
    #pragma unroll
    for (int it = 0; it < (BQ * Dh / 4) / NT; ++it) {
        int e = it * NT + tid, row = e >> 5, c4 = e & 31;
        float4 val = reinterpret_cast<const float4*>(qg)[e];
        uint32_t h01 = cvt2(val.x, val.y), h23 = cvt2(val.z, val.w);
        uint32_t l01 = cvt2(val.x - bflo(h01), val.y - bfhi(h01));
        uint32_t l23 = cvt2(val.z - bflo(h23), val.w - bfhi(h23));
        int off = row * RSB + c4 * 8;
        *reinterpret_cast<uint2*>(smem + SM_QHI + off) = make_uint2(h01, h23);
        *reinterpret_cast<uint2*>(smem + SM_QLO + off) = make_uint2(l01, l23);
    }

    // per-lane ldmatrix base addresses
    const int m0 = wid * 16;
    const uint32_t qoff = sbase + SM_QHI + (m0 + (lane & 15)) * RSB + ((lane >> 4) & 1) * 16;
    const uint32_t koff = sbase + SM_KHI + ((lane & 7) + ((lane >> 4) & 1) * 8) * RSB + ((lane >> 3) & 1) * 16;
    const uint32_t voff = sbase + SM_VHI + ((lane & 7) + ((lane >> 3) & 1) * 8) * RSB + ((lane >> 4) & 1) * 16;
    constexpr int DQL = SM_QLO - SM_QHI;
    constexpr int DKL = SM_KLO - SM_KHI;
    constexpr int DVL = SM_VLO - SM_VHI;

    float o[64];
    #pragma unroll
    for (int i = 0; i < 64; ++i) o[i] = 0.0f;
    float M0 = -INFINITY, M1 = -INFINITY, L0 = 0.0f, L1 = 0.0f;

    const int rg0 = q0 + m0 + (lane >> 2);   // global q row (upper)
    const int rg1 = rg0 + 8;
    const int c00 = 2 * (lane & 3);          // local col base within n8 tile

    for (int kt = 0; kt < nkt; ++kt) {
        __syncthreads();
        // ---- load K,V tiles, split to hi/lo ----
        const float* kgt = kg + (size_t)kt * BK * Dh;
        const float* vgt = vg + (size_t)kt * BK * Dh;
        #pragma unroll
        for (int it = 0; it < (BK * Dh / 4) / NT; ++it) {
            int e = it * NT + tid, row = e >> 5, c4 = e & 31;
            int off = row * RSB + c4 * 8;
            float4 kv4 = reinterpret_cast<const float4*>(kgt)[e];
            uint32_t h01 = cvt2(kv4.x, kv4.y), h23 = cvt2(kv4.z, kv4.w);
            uint32_t l01 = cvt2(kv4.x - bflo(h01), kv4.y - bfhi(h01));
            uint32_t l23 = cvt2(kv4.z - bflo(h23), kv4.w - bfhi(h23));
            *reinterpret_cast<uint2*>(smem + SM_KHI + off) = make_uint2(h01, h23);
            *reinterpret_cast<uint2*>(smem + SM_KLO + off) = make_uint2(l01, l23);
            float4 vv4 = reinterpret_cast<const float4*>(vgt)[e];
            h01 = cvt2(vv4.x, vv4.y); h23 = cvt2(vv4.z, vv4.w);
            l01 = cvt2(vv4.x - bflo(h01), vv4.y - bfhi(h01));
            l23 = cvt2(vv4.z - bflo(h23), vv4.w - bfhi(h23));
            *reinterpret_cast<uint2*>(smem + SM_VHI + off) = make_uint2(h01, h23);
            *reinterpret_cast<uint2*>(smem + SM_VLO + off) = make_uint2(l01, l23);
        }
        if (tid < BK) am_s[tid] = amg[kt * BK + tid];
        __syncthreads();

        // ---- S = Q K^T (3-pass split, 16x64 per warp) ----
        float sv[32];
        #pragma unroll
        for (int i = 0; i < 32; ++i) sv[i] = 0.0f;
        #pragma unroll
        for (int t = 0; t < 8; ++t) {                 // k16 tiles over d=128
            uint32_t ah[4], al[4];
            ldsm4(ah, qoff + t * 32);
            ldsm4(al, qoff + DQL + t * 32);
            #pragma unroll
            for (int g = 0; g < 4; ++g) {             // n16 groups over 64 cols
                uint32_t bh4[4], bl4[4];
                ldsm4(bh4, koff + g * (16 * RSB) + t * 32);
                ldsm4(bl4, koff + DKL + g * (16 * RSB) + t * 32);
                mma_bf16(sv + 8 * g,     ah, bh4);
                mma_bf16(sv + 8 * g,     ah, bl4);
                mma_bf16(sv + 8 * g,     al, bh4);
                mma_bf16(sv + 8 * g + 4, ah, bh4 + 2);
                mma_bf16(sv + 8 * g + 4, ah, bl4 + 2);
                mma_bf16(sv + 8 * g + 4, al, bh4 + 2);
            }
        }

        // ---- causal mask + additive attn_mask ----
        float amr[16];
        #pragma unroll
        for (int n = 0; n < 8; ++n) {
            float2 a2 = *reinterpret_cast<const float2*>(&am_s[8 * n + c00]);
            amr[2 * n] = a2.x; amr[2 * n + 1] = a2.y;
        }
        if (kt >= nkt - 2) {   // only diagonal-touching tiles need element checks
            #pragma unroll
            for (int n = 0; n < 8; ++n) {
                int cg = kt * BK + 8 * n + c00;
                sv[4*n+0] = (cg     <= rg0) ? sv[4*n+0] + amr[2*n]   : -1e30f;
                sv[4*n+1] = (cg + 1 <= rg0) ? sv[4*n+1] + amr[2*n+1] : -1e30f;
                sv[4*n+2] = (cg     <= rg1) ? sv[4*n+2] + amr[2*n]   : -1e30f;
                sv[4*n+3] = (cg + 1 <= rg1) ? sv[4*n+3] + amr[2*n+1] : -1e30f;
            }
        } else {
            #pragma unroll
            for (int n = 0; n < 8; ++n) {
                sv[4*n+0] += amr[2*n];   sv[4*n+1] += amr[2*n+1];
                sv[4*n+2] += amr[2*n];   sv[4*n+3] += amr[2*n+1];
            }
        }

        // ---- online softmax (intra-quad shuffles only) ----
        float t0 = -INFINITY, t1 = -INFINITY;
        #pragma unroll
        for (int n = 0; n < 8; ++n) {
            t0 = fmaxf(t0, fmaxf(sv[4*n+0], sv[4*n+1]));
            t1 = fmaxf(t1, fmaxf(sv[4*n+2], sv[4*n+3]));
        }
        t0 = fmaxf(t0, __shfl_xor_sync(0xffffffffu, t0, 1));
        t0 = fmaxf(t0, __shfl_xor_sync(0xffffffffu, t0, 2));
        t1 = fmaxf(t1, __shfl_xor_sync(0xffffffffu, t1, 1));
        t1 = fmaxf(t1, __shfl_xor_sync(0xffffffffu, t1, 2));
        float M0n = fmaxf(M0, t0), M1n = fmaxf(M1, t1);
        float a0 = fexp(M0 - M0n), a1 = fexp(M1 - M1n);
        M0 = M0n; M1 = M1n;

        float l0 = 0.0f, l1 = 0.0f;
        #pragma unroll
        for (int n = 0; n < 8; ++n) {
            sv[4*n+0] = fexp(sv[4*n+0] - M0n);
            sv[4*n+1] = fexp(sv[4*n+1] - M0n);
            l0 += sv[4*n+0] + sv[4*n+1];
            sv[4*n+2] = fexp(sv[4*n+2] - M1n);
            sv[4*n+3] = fexp(sv[4*n+3] - M1n);
            l1 += sv[4*n+2] + sv[4*n+3];
        }
        l0 += __shfl_xor_sync(0xffffffffu, l0, 1);
        l0 += __shfl_xor_sync(0xffffffffu, l0, 2);
        l1 += __shfl_xor_sync(0xffffffffu, l1, 1);
        l1 += __shfl_xor_sync(0xffffffffu, l1, 2);
        L0 = L0 * a0 + l0;
        L1 = L1 * a1 + l1;
        #pragma unroll
        for (int n = 0; n < 16; ++n) {
            o[4*n+0] *= a0; o[4*n+1] *= a0;
            o[4*n+2] *= a1; o[4*n+3] *= a1;
        }

        // ---- P -> bf16 hi/lo A-fragments (pure register shuffle-free) ----
        uint32_t ph[4][4], pl[4][4];
        #pragma unroll
        for (int t = 0; t < 4; ++t) {
            #pragma unroll
            for (int rix = 0; rix < 4; ++rix) {
                float f0 = sv[8*t + 2*rix], f1 = sv[8*t + 2*rix + 1];
                uint32_t hh = cvt2(f0, f1);
                ph[t][rix] = hh;
                pl[t][rix] = cvt2(f0 - bflo(hh), f1 - bfhi(hh));
            }
        }

        // ---- O += P V (3-pass split, 16x128 per warp) ----
        #pragma unroll
        for (int t = 0; t < 4; ++t) {                 // k16 tiles over BK=64
            #pragma unroll
            for (int g = 0; g < 8; ++g) {             // n16 groups over d=128
                uint32_t vh4[4], vl4[4];
                ldsm4t(vh4, voff + t * (16 * RSB) + g * 32);
                ldsm4t(vl4, voff + DVL + t * (16 * RSB) + g * 32);
                mma_bf16(o + 8 * g,     ph[t], vh4);
                mma_bf16(o + 8 * g,     ph[t], vl4);
                mma_bf16(o + 8 * g,     pl[t], vh4);
                mma_bf16(o + 8 * g + 4, ph[t], vh4 + 2);
                mma_bf16(o + 8 * g + 4, ph[t], vl4 + 2);
                mma_bf16(o + 8 * g + 4, pl[t], vh4 + 2);
            }
        }
    }

    // ---- epilogue: normalize, head_mask, store ----
    float li0 = hmv / L0, li1 = hmv / L1;
    float* o0 = out + ((size_t)bh * Sn + rg0) * Dh;
    float* o1 = o0 + 8 * Dh;
    #pragma unroll
    for (int n = 0; n < 16; ++n) {
        int c = 8 * n + c00;
        *reinterpret_cast<float2*>(o0 + c) = make_float2(o[4*n+0] * li0, o[4*n+1] * li0);
        *reinterpret_cast<float2*>(o1 + c) = make_float2(o[4*n+2] * li1, o[4*n+3] * li1);
    }
}

// ===================== launch =====================
extern "C" void kernel_launch(void* const* d_in, const int* in_sizes, int n_in,
                              void* d_out, int out_size)
{
    const float* q  = (const float*)d_in[0];
    const float* k  = (const float*)d_in[1];
    const float* v  = (const float*)d_in[2];
    const float* am = (const float*)d_in[3];
    const float* hm = (const float*)d_in[4];
    float* out = (float*)d_out;

    cudaFuncSetAttribute(fa_mma_kernel,
                         cudaFuncAttributeMaxDynamicSharedMemorySize, SM_TOTAL);

    dim3 grid(Sn / BQ, Bsz * Hn);   // (16 q-tiles, 32 bh)
    fa_mma_kernel<<<grid, NT, SM_TOTAL>>>(q, k, v, am, hm, out);
}